// round 3
// baseline (speedup 1.0000x reference)
#include <cuda_runtime.h>
#include <math.h>

// B=8, CIN=16, CO=64, N=512, L=60, K=3
// out = out[8,64,512,60] | adj_out[8,512,512] | T_coef[8,60,60]  (fp32)
#define OUT_ADJ 15728640
#define OUT_TC  17825792

// ----------------------------- device scratch ------------------------------
static __device__ float d_x_in[15728640];   // [b,c,n,l]
static __device__ float d_x1 [15728640];    // [b,c,n,l]
static __device__ float d_x1t[15728640];    // [b,n,c,l]
static __device__ float d_g1a[1048576];     // [b,n,4,64]
static __device__ float d_g2a[1048576];
static __device__ float d_g1b[3145728];     // [b,n,12,64]
static __device__ float d_g2b[3145728];
static __device__ float d_S  [33554432];    // [t,b,n,q]  == LSTM X rows
static __device__ float d_XW [134217728];   // [t*4096+bn, 2048]
static __device__ float d_HG [8388608];     // [4096, 2048]
static __device__ float d_h  [2097152];     // [4096, 512]
static __device__ float d_c  [2097152];
static __device__ float d_adj1[2097152];    // [b,512,512]
static __device__ float d_T2 [2097152];
static __device__ float d_xgT1[15728640];   // [b,q,c,l]
static __device__ float d_xgT2[15728640];
static __device__ float d_x1b[15728640];    // [b,c,n,l]
static __device__ float d_f1 [245760];      // [b,l,n]
static __device__ float d_f2 [30720];       // [b,c,l]
static __device__ float d_tmp[30720];       // [b,l,c]
static __device__ float d_lgsig[28800];     // [b,l,q]
static __device__ float d_lg2[28800];       // [b,i,t]
static __device__ float d_bn_mu[60];
static __device__ float d_bn_rstd[60];
static __device__ float d_Tc [28800];       // [b,i,t]
static __device__ float d_x2 [15728640];    // [b,c,n,q] -> y (in place)
static __device__ float d_psum[61440];
static __device__ float d_psq [61440];
static __device__ float d_mu  [8];
static __device__ float d_rstd[8];

__device__ __forceinline__ float sigf(float x)  { return 1.f / (1.f + expf(-x)); }
__device__ __forceinline__ float lrelu(float x) { return x > 0.f ? x : 0.01f * x; }

__global__ void k_zero(float* p, int n) {
    int i = blockIdx.x * 256 + threadIdx.x;
    if (i < n) p[i] = 0.f;
}

// ---------------------------------------------------------------------------
// conv1 (1x1) + tconv (1x3,pad1)+lrelu, + attention feature projections.
// One block per (n, b), 256 threads.
// ---------------------------------------------------------------------------
__global__ void __launch_bounds__(256) k_prep(
    const float* __restrict__ x,
    const float* __restrict__ c1w, const float* __restrict__ c1b,
    const float* __restrict__ tw,  const float* __restrict__ tb,
    const float* __restrict__ w3a, const float* __restrict__ w3b,
    const float* __restrict__ w2a, const float* __restrict__ w2b)
{
    int n = blockIdx.x, b = blockIdx.y, tid = threadIdx.x;
    __shared__ float xs[16][62];
    __shared__ float x1s[64][60];

    for (int i = tid; i < 16 * 60; i += 256) {
        int ci = i / 60, l = i - ci * 60;
        xs[ci][l + 1] = x[((b * 16 + ci) * 512 + n) * 60 + l];
    }
    if (tid < 16) { xs[tid][0] = 0.f; xs[tid][61] = 0.f; }
    __syncthreads();

    for (int i = tid; i < 64 * 60; i += 256) {
        int co = i / 60, l = i - co * 60;
        float a0 = c1b[co], a1 = tb[co];
        #pragma unroll
        for (int ci = 0; ci < 16; ci++) {
            float vm = xs[ci][l], v0 = xs[ci][l + 1], vp = xs[ci][l + 2];
            a0 += v0 * c1w[co * 16 + ci];
            const float* w = tw + (co * 16 + ci) * 3;
            a1 += vm * w[0] + v0 * w[1] + vp * w[2];
        }
        int gi = ((b * 64 + co) * 512 + n) * 60 + l;
        d_x_in[gi] = a0;
        float v1 = lrelu(a1);
        d_x1[gi] = v1;
        d_x1t[((b * 512 + n) * 64 + co) * 60 + l] = v1;
        x1s[co][l] = v1;
    }
    __syncthreads();

    {   // _satt3 features: channel-group layout o = c*4+m, input cc = c*12+j
        int o = tid >> 2, r = tid & 3;
        float s1 = 0.f, s2 = 0.f;
        const float* wa = w3a + o * 768;
        const float* wb = w3b + o * 768;
        for (int c = 0; c < 64; c++) {
            #pragma unroll
            for (int j = 0; j < 12; j++) {
                float v = x1s[c][j * 4 + r];
                s1 += v * wa[c * 12 + j];
                s2 += v * wb[c * 12 + j];
            }
        }
        int gi = ((b * 512 + n) * 4 + r) * 64 + o;
        d_g1a[gi] = s1; d_g2a[gi] = s2;
    }
    for (int i = tid; i < 768; i += 256) {   // _satt features on t=48..59
        int o = i / 12, r = i - o * 12;
        float s1 = 0.f, s2 = 0.f;
        const float* wa = w2a + o * 64;
        const float* wb = w2b + o * 64;
        #pragma unroll
        for (int c = 0; c < 64; c++) {
            float v = x1s[c][48 + r];
            s1 += v * wa[c];
            s2 += v * wb[c];
        }
        int gi = ((b * 512 + n) * 12 + r) * 64 + o;
        d_g1b[gi] = s1; d_g2b[gi] = s2;
    }
}

// ---------------------------------------------------------------------------
// S[t,b,n,q] = 0.25 * sum_m sigmoid( sum_c16 g1[n,4c+m]*g2[q,4c+m] )
// ---------------------------------------------------------------------------
__global__ void __launch_bounds__(1024) k_satt()
{
    int bz = blockIdx.z;
    int b = bz >> 4, t = bz & 15;
    int n0 = blockIdx.y * 32, q0 = blockIdx.x * 32;
    const float *g1, *g2; int strd;
    if (t < 4) { strd = 256; g1 = d_g1a + (size_t)b * 512 * 256 + t * 64;
                             g2 = d_g2a + (size_t)b * 512 * 256 + t * 64; }
    else       { strd = 768; g1 = d_g1b + (size_t)b * 512 * 768 + (t - 4) * 64;
                             g2 = d_g2b + (size_t)b * 512 * 768 + (t - 4) * 64; }
    __shared__ float As[32][65], Bs[32][65];
    int tx = threadIdx.x, ty = threadIdx.y;
    int tid = ty * 32 + tx;
    for (int e = tid; e < 2048; e += 1024) {
        int nn = e >> 6, o = e & 63;
        As[nn][o] = g1[(n0 + nn) * strd + o];
        Bs[nn][o] = g2[(q0 + nn) * strd + o];
    }
    __syncthreads();
    float a0 = 0.f, a1 = 0.f, a2 = 0.f, a3 = 0.f;
    #pragma unroll
    for (int c = 0; c < 16; c++) {
        a0 += As[ty][c * 4 + 0] * Bs[tx][c * 4 + 0];
        a1 += As[ty][c * 4 + 1] * Bs[tx][c * 4 + 1];
        a2 += As[ty][c * 4 + 2] * Bs[tx][c * 4 + 2];
        a3 += As[ty][c * 4 + 3] * Bs[tx][c * 4 + 3];
    }
    float s = 0.25f * (sigf(a0) + sigf(a1) + sigf(a2) + sigf(a3));
    d_S[(((size_t)t * 8 + b) * 512 + n0 + ty) * 512 + q0 + tx] = s;
}

// ---------------------------------------------------------------------------
// Generic SGEMM: C = alpha * A(MxK) * op(B); op(B)=B(KxN) or B^T (B NxK).
// 128x128 tiles, BK=16, 256 threads, 8x8 microtile, batched via blockIdx.z.
// FULL=true: no bounds checks (all dims tile-divisible).
// ---------------------------------------------------------------------------
template <bool FULL>
__global__ void __launch_bounds__(256) k_sgemm(
    const float* __restrict__ A, const float* __restrict__ B, float* __restrict__ C,
    int M, int N, int K, int lda, int ldb, int ldc,
    long sA, long sB, long sC, int transB, float alpha)
{
    A += (long)blockIdx.z * sA;
    B += (long)blockIdx.z * sB;
    C += (long)blockIdx.z * sC;
    int m0 = blockIdx.y * 128, n0 = blockIdx.x * 128;
    __shared__ float As[16][132];
    __shared__ float Bs[16][132];
    int tid = threadIdx.x;
    int tx = tid & 15, ty = tid >> 4;
    float acc[8][8] = {};
    for (int k0 = 0; k0 < K; k0 += 16) {
        #pragma unroll
        for (int r = 0; r < 8; r++) {
            int e = tid + r * 256;
            int m = e >> 4, kk = e & 15;
            float v;
            if (FULL) v = A[(long)(m0 + m) * lda + (k0 + kk)];
            else v = (m0 + m < M && k0 + kk < K) ? A[(long)(m0 + m) * lda + (k0 + kk)] : 0.f;
            As[kk][m] = v;
        }
        if (!transB) {
            #pragma unroll
            for (int r = 0; r < 8; r++) {
                int e = tid + r * 256;
                int kk = e >> 7, n = e & 127;
                float v;
                if (FULL) v = B[(long)(k0 + kk) * ldb + (n0 + n)];
                else v = (k0 + kk < K && n0 + n < N) ? B[(long)(k0 + kk) * ldb + (n0 + n)] : 0.f;
                Bs[kk][n] = v;
            }
        } else {
            #pragma unroll
            for (int r = 0; r < 8; r++) {
                int e = tid + r * 256;
                int n = e >> 4, kk = e & 15;
                float v;
                if (FULL) v = B[(long)(n0 + n) * ldb + (k0 + kk)];
                else v = (n0 + n < N && k0 + kk < K) ? B[(long)(n0 + n) * ldb + (k0 + kk)] : 0.f;
                Bs[kk][n] = v;
            }
        }
        __syncthreads();
        #pragma unroll
        for (int kk = 0; kk < 16; kk++) {
            float a[8], bb[8];
            #pragma unroll
            for (int i = 0; i < 8; i++) a[i] = As[kk][ty * 8 + i];
            #pragma unroll
            for (int j = 0; j < 8; j++) bb[j] = Bs[kk][tx * 8 + j];
            #pragma unroll
            for (int i = 0; i < 8; i++)
                #pragma unroll
                for (int j = 0; j < 8; j++) acc[i][j] += a[i] * bb[j];
        }
        __syncthreads();
    }
    #pragma unroll
    for (int i = 0; i < 8; i++) {
        int m = m0 + ty * 8 + i;
        if (!FULL && m >= M) continue;
        #pragma unroll
        for (int j = 0; j < 8; j++) {
            int n = n0 + tx * 8 + j;
            if (FULL || n < N) C[(long)m * ldc + n] = alpha * acc[i][j];
        }
    }
}

// ------------------------------ LSTM cell ----------------------------------
__global__ void k_cell(const float* __restrict__ bih, const float* __restrict__ bhh, int t)
{
    int idx = blockIdx.x * 256 + threadIdx.x;   // 4096*512
    int m = idx >> 9, j = idx & 511;
    const float* XWt = d_XW + (size_t)t * 4096 * 2048;
    size_t base = (size_t)m * 2048;
    float gi = XWt[base + j]        + d_HG[base + j]        + bih[j]        + bhh[j];
    float gf = XWt[base + 512 + j]  + d_HG[base + 512 + j]  + bih[512 + j]  + bhh[512 + j];
    float gg = XWt[base + 1024 + j] + d_HG[base + 1024 + j] + bih[1024 + j] + bhh[1024 + j];
    float go = XWt[base + 1536 + j] + d_HG[base + 1536 + j] + bih[1536 + j] + bhh[1536 + j];
    float c = d_c[idx];
    float cn = sigf(gf) * c + sigf(gi) * tanhf(gg);
    d_c[idx] = cn;
    d_h[idx] = sigf(go) * tanhf(cn);
}

__global__ void k_adj1(const float* __restrict__ supports, float* __restrict__ out_adj)
{
    int idx = blockIdx.x * 256 + threadIdx.x;
    float h = d_h[idx];
    out_adj[idx] = h;
    d_adj1[idx] = h * supports[idx];
}

__global__ void k_chebfix()
{
    int idx = blockIdx.x * 256 + threadIdx.x;   // 4096 = b*512+i
    int b = idx >> 9, i = idx & 511;
    d_T2[((size_t)b * 512 + i) * 512 + i] -= 1.f;
}

// ---------------------------------------------------------------------------
// GCN conv (1x3,pad1), 576-deep gathered GEMM, fused GLU epilogue.
// ---------------------------------------------------------------------------
__global__ void __launch_bounds__(256) k_gcn(const float* __restrict__ W, const float* __restrict__ bias)
{
    int b = blockIdx.y;
    int x0 = blockIdx.x * 64;
    int tid = threadIdx.x;
    int tx = tid & 15, ty = tid >> 4;
    __shared__ float Ws[16][130];
    __shared__ float Bs[16][68];
    float acc[8][4] = {};
    const float* src0 = d_x1t  + (size_t)b * 1966080;
    const float* src1 = d_xgT1 + (size_t)b * 1966080;
    const float* src2 = d_xgT2 + (size_t)b * 1966080;
    for (int k0 = 0; k0 < 576; k0 += 16) {
        #pragma unroll
        for (int r = 0; r < 8; r++) {
            int e = tid + r * 256;
            int o = e >> 4, kk = e & 15;
            Ws[kk][o] = W[o * 576 + k0 + kk];
        }
        #pragma unroll
        for (int r = 0; r < 4; r++) {
            int e = tid + r * 256;
            int kk = e >> 6, xx = e & 63;
            int k = k0 + kk;
            int cc = k / 3, d = k - cc * 3;
            int c = cc / 3, kch = cc - c * 3;
            int xg = x0 + xx;
            int q = xg / 60, l = xg - q * 60 + d - 1;
            float v = 0.f;
            if (l >= 0 && l < 60) {
                const float* s = (kch == 0) ? src0 : ((kch == 1) ? src1 : src2);
                v = s[(q * 64 + c) * 60 + l];
            }
            Bs[kk][xx] = v;
        }
        __syncthreads();
        #pragma unroll
        for (int kk = 0; kk < 16; kk++) {
            float w[8], bb[4];
            #pragma unroll
            for (int i = 0; i < 8; i++) w[i] = Ws[kk][ty + 16 * i];
            #pragma unroll
            for (int j = 0; j < 4; j++) bb[j] = Bs[kk][tx + 16 * j];
            #pragma unroll
            for (int i = 0; i < 8; i++)
                #pragma unroll
                for (int j = 0; j < 4; j++) acc[i][j] += w[i] * bb[j];
        }
        __syncthreads();
    }
    #pragma unroll
    for (int i = 0; i < 4; i++) {
        int o = ty + 16 * i;
        float bf = bias[o], bg = bias[o + 64];
        #pragma unroll
        for (int j = 0; j < 4; j++) {
            int xg = x0 + tx + 16 * j;
            int q = xg / 60, l = xg - q * 60;
            float f = acc[i][j] + bf;
            float g = acc[i + 4][j] + bg;
            d_x1b[(((size_t)b * 64 + o) * 512 + q) * 60 + l] = sigf(g) * lrelu(f);
        }
    }
}

// --------------------------- temporal attention ----------------------------
__global__ void k_f1(const float* __restrict__ tw1)
{
    int idx = blockIdx.x * 256 + threadIdx.x;   // 8*60*512
    int bl = idx >> 9, n = idx & 511;
    int b = bl / 60, l = bl - b * 60;
    const float* p = d_x1b + (size_t)b * 1966080 + n * 60 + l;
    float s = 0.f;
    #pragma unroll 8
    for (int c = 0; c < 64; c++) s += p[c * 30720] * tw1[c];
    d_f1[idx] = s;
}

__global__ void k_f2(const float* __restrict__ tw2)
{
    int bc = blockIdx.x;         // b*64+c
    int l = threadIdx.x;
    if (l >= 60) return;
    const float* p = d_x1b + (size_t)bc * 30720 + l;
    float s = 0.f;
    for (int n = 0; n < 512; n++) s += p[n * 60] * tw2[n];
    d_f2[bc * 60 + l] = s;
}

__global__ void k_tmp(const float* __restrict__ tw)
{
    int idx = blockIdx.x * 256 + threadIdx.x;   // 8*60*64
    int bl = idx >> 6, c = idx & 63;
    const float* f = d_f1 + bl * 512;
    float s = 0.f;
    for (int n = 0; n < 512; n++) s += f[n] * tw[n * 64 + c];
    d_tmp[idx] = s;
}

__global__ void k_lgb(const float* __restrict__ tbm)
{
    int idx = blockIdx.x * 256 + threadIdx.x;   // (b,l,q)
    if (idx >= 28800) return;
    int q = idx % 60; int bl = idx / 60;
    int l = bl % 60;
    float s = 0.f;
    int b = bl / 60;
    #pragma unroll 8
    for (int c = 0; c < 64; c++) s += d_tmp[bl * 64 + c] * d_f2[(b * 64 + c) * 60 + q];
    d_lgsig[idx] = sigf(s + tbm[l * 60 + q]);
}

__global__ void k_lgc(const float* __restrict__ tv)
{
    int idx = blockIdx.x * 256 + threadIdx.x;   // (b,i,t)
    if (idx >= 28800) return;
    int b = idx / 3600; int r = idx - b * 3600;
    int i = r / 60, t = r - i * 60;
    float s = 0.f;
    for (int q = 0; q < 60; q++) s += tv[i * 60 + q] * d_lgsig[(b * 60 + q) * 60 + t];
    d_lg2[idx] = s;
}

__global__ void k_bn()
{
    int t = blockIdx.x;
    __shared__ float ss[256], sq[256];
    float a = 0.f, b2 = 0.f;
    for (int s = threadIdx.x; s < 480; s += 256) {
        float v = d_lg2[s * 60 + t];
        a += v; b2 += v * v;
    }
    ss[threadIdx.x] = a; sq[threadIdx.x] = b2; __syncthreads();
    for (int st = 128; st > 0; st >>= 1) {
        if (threadIdx.x < st) { ss[threadIdx.x] += ss[threadIdx.x + st]; sq[threadIdx.x] += sq[threadIdx.x + st]; }
        __syncthreads();
    }
    if (threadIdx.x == 0) {
        float mu = ss[0] / 480.f;
        float var = sq[0] / 480.f - mu * mu;
        d_bn_mu[t] = mu;
        d_bn_rstd[t] = rsqrtf(var + 1e-5f);
    }
}

__global__ void k_soft(const float* __restrict__ bg, const float* __restrict__ bb, float* __restrict__ out_tc)
{
    int bi = blockIdx.x;             // b*60+i
    int i = bi % 60;
    int t = threadIdx.x;             // 64 threads
    __shared__ float sh[64];
    int blk_i = i < 12 ? 0 : (i < 24 ? 1 : (i < 36 ? 2 : 3));
    float z = -3.0e38f;
    if (t < 60) {
        float v = (d_lg2[bi * 60 + t] - d_bn_mu[t]) * d_bn_rstd[t] * bg[t] + bb[t];
        int blk_t = t < 12 ? 0 : (t < 24 ? 1 : (t < 36 ? 2 : 3));
        if (blk_t != blk_i) v += -1e13f;
        z = v;
    }
    sh[t] = z; __syncthreads();
    for (int s = 32; s > 0; s >>= 1) { if (t < s) sh[t] = fmaxf(sh[t], sh[t + s]); __syncthreads(); }
    float mx = sh[0]; __syncthreads();
    float e = (t < 60) ? expf(z - mx) : 0.f;
    sh[t] = e; __syncthreads();
    for (int s = 32; s > 0; s >>= 1) { if (t < s) sh[t] += sh[t + s]; __syncthreads(); }
    float inv = 1.f / sh[0];
    if (t < 60) {
        float val = e * inv;
        d_Tc[bi * 60 + t] = val;
        out_tc[bi * 60 + t] = val;
    }
}

// ------------------- residual + per-b LayerNorm ----------------------------
__global__ void k_ystats()
{
    int b = blockIdx.y;
    int e = blockIdx.x * 256 + threadIdx.x;     // 1966080 exactly
    size_t g = (size_t)b * 1966080 + e;
    float v = lrelu(d_x2[g]) + d_x_in[g];
    d_x2[g] = v;
    __shared__ float ss[256], sq[256];
    ss[threadIdx.x] = v; sq[threadIdx.x] = v * v; __syncthreads();
    for (int s = 128; s > 0; s >>= 1) {
        if (threadIdx.x < s) { ss[threadIdx.x] += ss[threadIdx.x + s]; sq[threadIdx.x] += sq[threadIdx.x + s]; }
        __syncthreads();
    }
    if (threadIdx.x == 0) {
        d_psum[b * 7680 + blockIdx.x] = ss[0];
        d_psq [b * 7680 + blockIdx.x] = sq[0];
    }
}

__global__ void k_lnstats2()
{
    int b = blockIdx.x;
    __shared__ float ss[256], sq[256];
    float a = 0.f, b2 = 0.f;
    for (int i = threadIdx.x; i < 7680; i += 256) {
        a += d_psum[b * 7680 + i]; b2 += d_psq[b * 7680 + i];
    }
    ss[threadIdx.x] = a; sq[threadIdx.x] = b2; __syncthreads();
    for (int s = 128; s > 0; s >>= 1) {
        if (threadIdx.x < s) { ss[threadIdx.x] += ss[threadIdx.x + s]; sq[threadIdx.x] += sq[threadIdx.x + s]; }
        __syncthreads();
    }
    if (threadIdx.x == 0) {
        float mu = ss[0] / 1966080.f;
        float var = sq[0] / 1966080.f - mu * mu;
        d_mu[b] = mu;
        d_rstd[b] = rsqrtf(var + 1e-5f);
    }
}

__global__ void k_lnfinal(const float* __restrict__ g, const float* __restrict__ bb, float* __restrict__ out)
{
    int b = blockIdx.y;
    int e = blockIdx.x * 256 + threadIdx.x;
    size_t idx = (size_t)b * 1966080 + e;
    out[idx] = (d_x2[idx] - d_mu[b]) * d_rstd[b] * g[e] + bb[e];
}

// ------------------------------- launcher ----------------------------------
extern "C" void kernel_launch(void* const* d_in, const int* in_sizes, int n_in,
                              void* d_out, int out_size) {
    const float* x    = (const float*)d_in[0];
    const float* sup  = (const float*)d_in[1];
    const float* c1w  = (const float*)d_in[2];
    const float* c1b  = (const float*)d_in[3];
    const float* tw   = (const float*)d_in[4];
    const float* tb   = (const float*)d_in[5];
    const float* s3w1 = (const float*)d_in[6];
    const float* s3w2 = (const float*)d_in[7];
    const float* s2w1 = (const float*)d_in[8];
    const float* s2w2 = (const float*)d_in[9];
    const float* wih  = (const float*)d_in[10];
    const float* whh  = (const float*)d_in[11];
    const float* bih  = (const float*)d_in[12];
    const float* bhh  = (const float*)d_in[13];
    const float* gw   = (const float*)d_in[14];
    const float* gb   = (const float*)d_in[15];
    const float* tw1  = (const float*)d_in[16];
    const float* tw2  = (const float*)d_in[17];
    const float* twm  = (const float*)d_in[18];
    const float* tbm  = (const float*)d_in[19];
    const float* tv   = (const float*)d_in[20];
    const float* bng  = (const float*)d_in[21];
    const float* bnb  = (const float*)d_in[22];
    const float* lng  = (const float*)d_in[23];
    const float* lnb  = (const float*)d_in[24];
    float* out = (float*)d_out;

    float *pS, *pXW, *pHG, *pH, *pC, *pA1, *pT2, *pX1T, *pXG1, *pXG2, *pX1B, *pTc, *pX2;
    cudaGetSymbolAddress((void**)&pS,   d_S);
    cudaGetSymbolAddress((void**)&pXW,  d_XW);
    cudaGetSymbolAddress((void**)&pHG,  d_HG);
    cudaGetSymbolAddress((void**)&pH,   d_h);
    cudaGetSymbolAddress((void**)&pC,   d_c);
    cudaGetSymbolAddress((void**)&pA1,  d_adj1);
    cudaGetSymbolAddress((void**)&pT2,  d_T2);
    cudaGetSymbolAddress((void**)&pX1T, d_x1t);
    cudaGetSymbolAddress((void**)&pXG1, d_xgT1);
    cudaGetSymbolAddress((void**)&pXG2, d_xgT2);
    cudaGetSymbolAddress((void**)&pX1B, d_x1b);
    cudaGetSymbolAddress((void**)&pTc,  d_Tc);
    cudaGetSymbolAddress((void**)&pX2,  d_x2);

    // ---- prep + attention -> S ----
    k_prep<<<dim3(512, 8), 256>>>(x, c1w, c1b, tw, tb, s3w1, s3w2, s2w1, s2w2);
    k_satt<<<dim3(16, 16, 128), dim3(32, 32)>>>();

    // ---- LSTM ----
    k_zero<<<32768, 256>>>(pHG, 8388608);
    k_zero<<<8192, 256>>>(pC, 2097152);
    k_sgemm<true><<<dim3(16, 512, 1), 256>>>(pS, wih, pXW, 65536, 2048, 512,
                                             512, 512, 2048, 0, 0, 0, 1, 1.f);
    for (int t = 0; t < 16; t++) {
        if (t) k_sgemm<true><<<dim3(16, 32, 1), 256>>>(pH, whh, pHG, 4096, 2048, 512,
                                                       512, 512, 2048, 0, 0, 0, 1, 1.f);
        k_cell<<<8192, 256>>>(bih, bhh, t);
    }

    // ---- Chebyshev + graph einsum ----
    k_adj1<<<8192, 256>>>(sup, out + OUT_ADJ);
    k_sgemm<true><<<dim3(4, 4, 8), 256>>>(pA1, pA1, pT2, 512, 512, 512,
                                          512, 512, 512, 262144, 262144, 262144, 0, 2.f);
    k_chebfix<<<16, 256>>>();
    k_sgemm<true><<<dim3(30, 4, 8), 256>>>(pA1, pX1T, pXG1, 512, 3840, 512,
                                           512, 3840, 3840, 262144, 1966080, 1966080, 0, 1.f);
    k_sgemm<true><<<dim3(30, 4, 8), 256>>>(pT2, pX1T, pXG2, 512, 3840, 512,
                                           512, 3840, 3840, 262144, 1966080, 1966080, 0, 1.f);

    // ---- GCN conv + GLU ----
    k_gcn<<<dim3(480, 8), 256>>>(gw, gb);

    // ---- temporal attention ----
    k_f1<<<960, 256>>>(tw1);
    k_f2<<<512, 64>>>(tw2);
    k_tmp<<<120, 256>>>(twm);
    k_lgb<<<113, 256>>>(tbm);
    k_lgc<<<113, 256>>>(tv);
    k_bn<<<60, 256>>>();
    k_soft<<<480, 64>>>(bng, bnb, out + OUT_TC);

    // ---- x2 = x1b @ T_coef^T ----
    k_sgemm<false><<<dim3(1, 256, 8), 256>>>(pX1B, pTc, pX2, 32768, 60, 60,
                                             60, 60, 60, 1966080, 3600, 1966080, 1, 1.f);

    // ---- residual + LayerNorm ----
    k_ystats<<<dim3(7680, 8), 256>>>();
    k_lnstats2<<<8, 256>>>();
    k_lnfinal<<<dim3(7680, 8), 256>>>(lng, lnb, out);
}

// round 5
// speedup vs baseline: 2.3405x; 2.3405x over previous
#include <cuda_runtime.h>
#include <math.h>

// B=8, CIN=16, CO=64, N=512, L=60, K=3
// out = out[8,64,512,60] | adj_out[8,512,512] | T_coef[8,60,60]  (fp32)
#define OUT_ADJ 15728640
#define OUT_TC  17825792

// ----------------------------- device scratch ------------------------------
static __device__ float d_x_in[15728640];   // [b,c,n,l]
static __device__ float d_x1t[15728640];    // [b,n,c,l]
static __device__ float d_g1a[1048576];     // [b,n,4,64]
static __device__ float d_g2a[1048576];
static __device__ float d_g1b[3145728];     // [b,n,12,64]
static __device__ float d_g2b[3145728];
static __device__ float d_S  [33554432];    // [t,b,n,q]  == LSTM X rows
static __device__ float d_XW [134217728];   // [t*4096+bn, 2048]
static __device__ float d_HG [8388608];     // [4096, 2048]
static __device__ float d_h  [2097152];     // [4096, 512]
static __device__ float d_c  [2097152];
static __device__ float d_adj1[2097152];    // [b,512,512]
static __device__ float d_T2 [2097152];
static __device__ float d_xgT1[15728640];   // [b,q,c,l]
static __device__ float d_xgT2[15728640];
static __device__ float d_xg [31457280];    // [b,128,30720] raw gcn conv out
static __device__ float d_x1b[15728640];    // [b,c,n,l]
static __device__ float d_f1 [245760];      // [b,l,n]
static __device__ float d_f2 [30720];       // [b,c,l]
static __device__ float d_tmp[30720];       // [b,l,c]
static __device__ float d_lgsig[28800];     // [b,l,q]
static __device__ float d_lg2[28800];       // [b,i,t]
static __device__ float d_bn_mu[60];
static __device__ float d_bn_rstd[60];
static __device__ float d_Tc [28800];       // [b,i,t]
static __device__ float d_x2 [15728640];    // [b,c,n,q] -> y (in place)
static __device__ float d_psum[61440];
static __device__ float d_psq [61440];
static __device__ float d_mu  [8];
static __device__ float d_rstd[8];

__device__ __forceinline__ float sigf(float x)  { return 1.f / (1.f + expf(-x)); }
__device__ __forceinline__ float lrelu(float x) { return x > 0.f ? x : 0.01f * x; }

__device__ __forceinline__ unsigned f2tf(float x) {
    unsigned r;
    asm("cvt.rna.tf32.f32 %0, %1;" : "=r"(r) : "f"(x));
    return r;
}

__device__ __forceinline__ void mma8(float* d, const unsigned* a, const unsigned* b) {
    asm volatile(
        "mma.sync.aligned.m16n8k8.row.col.f32.tf32.tf32.f32 "
        "{%0,%1,%2,%3}, {%4,%5,%6,%7}, {%8,%9}, {%0,%1,%2,%3};\n"
        : "+f"(d[0]), "+f"(d[1]), "+f"(d[2]), "+f"(d[3])
        : "r"(a[0]), "r"(a[1]), "r"(a[2]), "r"(a[3]), "r"(b[0]), "r"(b[1]));
}

// ---------------------------------------------------------------------------
// conv1 (1x1) + tconv (1x3,pad1)+lrelu, + attention feature projections.
// ---------------------------------------------------------------------------
__global__ void __launch_bounds__(256) k_prep(
    const float* __restrict__ x,
    const float* __restrict__ c1w, const float* __restrict__ c1b,
    const float* __restrict__ tw,  const float* __restrict__ tb,
    const float* __restrict__ w3a, const float* __restrict__ w3b,
    const float* __restrict__ w2a, const float* __restrict__ w2b)
{
    int n = blockIdx.x, b = blockIdx.y, tid = threadIdx.x;
    __shared__ float xs[16][62];
    __shared__ float x1s[64][60];

    for (int i = tid; i < 16 * 60; i += 256) {
        int ci = i / 60, l = i - ci * 60;
        xs[ci][l + 1] = x[((b * 16 + ci) * 512 + n) * 60 + l];
    }
    if (tid < 16) { xs[tid][0] = 0.f; xs[tid][61] = 0.f; }
    __syncthreads();

    for (int i = tid; i < 64 * 60; i += 256) {
        int co = i / 60, l = i - co * 60;
        float a0 = c1b[co], a1 = tb[co];
        #pragma unroll
        for (int ci = 0; ci < 16; ci++) {
            float vm = xs[ci][l], v0 = xs[ci][l + 1], vp = xs[ci][l + 2];
            a0 += v0 * c1w[co * 16 + ci];
            const float* w = tw + (co * 16 + ci) * 3;
            a1 += vm * w[0] + v0 * w[1] + vp * w[2];
        }
        d_x_in[((b * 64 + co) * 512 + n) * 60 + l] = a0;
        float v1 = lrelu(a1);
        d_x1t[((b * 512 + n) * 64 + co) * 60 + l] = v1;
        x1s[co][l] = v1;
    }
    __syncthreads();

    {   // _satt3 features
        int o = tid >> 2, r = tid & 3;
        float s1 = 0.f, s2 = 0.f;
        const float* wa = w3a + o * 768;
        const float* wb = w3b + o * 768;
        for (int c = 0; c < 64; c++) {
            #pragma unroll
            for (int j = 0; j < 12; j++) {
                float v = x1s[c][j * 4 + r];
                s1 += v * wa[c * 12 + j];
                s2 += v * wb[c * 12 + j];
            }
        }
        int gi = ((b * 512 + n) * 4 + r) * 64 + o;
        d_g1a[gi] = s1; d_g2a[gi] = s2;
    }
    for (int i = tid; i < 768; i += 256) {   // _satt features on t=48..59
        int o = i / 12, r = i - o * 12;
        float s1 = 0.f, s2 = 0.f;
        const float* wa = w2a + o * 64;
        const float* wb = w2b + o * 64;
        #pragma unroll
        for (int c = 0; c < 64; c++) {
            float v = x1s[c][48 + r];
            s1 += v * wa[c];
            s2 += v * wb[c];
        }
        int gi = ((b * 512 + n) * 12 + r) * 64 + o;
        d_g1b[gi] = s1; d_g2b[gi] = s2;
    }
}

// ---------------------------------------------------------------------------
// S[t,b,n,q] = 0.25 * sum_m sigmoid( sum_c16 g1[n,4c+m]*g2[q,4c+m] )
// ---------------------------------------------------------------------------
__global__ void __launch_bounds__(1024) k_satt()
{
    int bz = blockIdx.z;
    int b = bz >> 4, t = bz & 15;
    int n0 = blockIdx.y * 32, q0 = blockIdx.x * 32;
    const float *g1, *g2; int strd;
    if (t < 4) { strd = 256; g1 = d_g1a + (size_t)b * 512 * 256 + t * 64;
                             g2 = d_g2a + (size_t)b * 512 * 256 + t * 64; }
    else       { strd = 768; g1 = d_g1b + (size_t)b * 512 * 768 + (t - 4) * 64;
                             g2 = d_g2b + (size_t)b * 512 * 768 + (t - 4) * 64; }
    __shared__ float As[32][65], Bs[32][65];
    int tx = threadIdx.x, ty = threadIdx.y;
    int tid = ty * 32 + tx;
    for (int e = tid; e < 2048; e += 1024) {
        int nn = e >> 6, o = e & 63;
        As[nn][o] = g1[(n0 + nn) * strd + o];
        Bs[nn][o] = g2[(q0 + nn) * strd + o];
    }
    __syncthreads();
    float a0 = 0.f, a1 = 0.f, a2 = 0.f, a3 = 0.f;
    #pragma unroll
    for (int c = 0; c < 16; c++) {
        a0 += As[ty][c * 4 + 0] * Bs[tx][c * 4 + 0];
        a1 += As[ty][c * 4 + 1] * Bs[tx][c * 4 + 1];
        a2 += As[ty][c * 4 + 2] * Bs[tx][c * 4 + 2];
        a3 += As[ty][c * 4 + 3] * Bs[tx][c * 4 + 3];
    }
    float s = 0.25f * (sigf(a0) + sigf(a1) + sigf(a2) + sigf(a3));
    d_S[(((size_t)t * 8 + b) * 512 + n0 + ty) * 512 + q0 + tx] = s;
}

// ---------------------------------------------------------------------------
// tf32 tensor-core GEMM. C = alpha * A(MxK) * op(B).
// BMODE 0: B is K x N row-major.  BMODE 1: B is N x K row-major (B^T).
// BMODE 2: GCN im2col gather B (K=576, N=30720), batch via blockIdx.z.
// Block tile 128x128, BK=32, 256 threads (8 warps, 2m x 4n), warp 64x32.
// All M, N, K must be multiples of 128/128/32.
// ---------------------------------------------------------------------------
template <int BMODE>
__global__ void __launch_bounds__(256) k_mma(
    const float* __restrict__ A, const float* __restrict__ B, float* __restrict__ C,
    int M, int N, int K, int lda, int ldb, int ldc,
    long sA, long sB, long sC, float alpha)
{
    A += (long)blockIdx.z * sA;
    B += (long)blockIdx.z * sB;
    C += (long)blockIdx.z * sC;
    const float* g0 = d_x1t  + (long)blockIdx.z * 1966080;
    const float* g1 = d_xgT1 + (long)blockIdx.z * 1966080;
    const float* g2 = d_xgT2 + (long)blockIdx.z * 1966080;

    int m0 = blockIdx.y * 128, n0 = blockIdx.x * 128;
    int tid = threadIdx.x;
    int warp = tid >> 5, lane = tid & 31;
    int wm = (warp & 1) * 64, wn = (warp >> 1) * 32;
    int g = lane >> 2, t = lane & 3;

    __shared__ unsigned AsM[128][36];        // [m][k]
    __shared__ unsigned BsM[4608];           // mode0/2: [k][n] stride 136; mode1: [n][k] stride 36

    float acc[4][4][4];
    #pragma unroll
    for (int i = 0; i < 4; i++)
        #pragma unroll
        for (int j = 0; j < 4; j++)
            #pragma unroll
            for (int e = 0; e < 4; e++) acc[i][j][e] = 0.f;

    int ar = tid >> 3, ak = (tid & 7) << 2;

    for (int k0 = 0; k0 < K; k0 += 32) {
        // ---- load A tile -> AsM[m][k] ----
        #pragma unroll
        for (int p = 0; p < 4; p++) {
            const float4 v = *reinterpret_cast<const float4*>(A + (long)(m0 + ar + 32 * p) * lda + k0 + ak);
            unsigned* dst = &AsM[ar + 32 * p][ak];
            dst[0] = f2tf(v.x); dst[1] = f2tf(v.y); dst[2] = f2tf(v.z); dst[3] = f2tf(v.w);
        }
        // ---- load B tile ----
        if (BMODE == 0) {
            int kk = tid >> 5, n4 = (tid & 31) << 2;
            #pragma unroll
            for (int p = 0; p < 4; p++) {
                const float4 v = *reinterpret_cast<const float4*>(B + (long)(k0 + kk + 8 * p) * ldb + n0 + n4);
                unsigned* dst = &BsM[(kk + 8 * p) * 136 + n4];
                dst[0] = f2tf(v.x); dst[1] = f2tf(v.y); dst[2] = f2tf(v.z); dst[3] = f2tf(v.w);
            }
        } else if (BMODE == 1) {
            #pragma unroll
            for (int p = 0; p < 4; p++) {
                const float4 v = *reinterpret_cast<const float4*>(B + (long)(n0 + ar + 32 * p) * ldb + k0 + ak);
                unsigned* dst = &BsM[(ar + 32 * p) * 36 + ak];
                dst[0] = f2tf(v.x); dst[1] = f2tf(v.y); dst[2] = f2tf(v.z); dst[3] = f2tf(v.w);
            }
        } else {
            int kk = tid >> 3, nb = (tid & 7) << 4;
            int k = k0 + kk;
            int cc = k / 3, d = k - cc * 3;
            int c = cc / 3, kch = cc - c * 3;
            const float* src = (kch == 0) ? g0 : ((kch == 1) ? g1 : g2);
            #pragma unroll
            for (int i = 0; i < 16; i++) {
                int n = n0 + nb + i;
                int q = n / 60, l = n - q * 60 + d - 1;
                float v = 0.f;
                if (l >= 0 && l < 60) v = src[(q * 64 + c) * 60 + l];
                BsM[kk * 136 + nb + i] = f2tf(v);
            }
        }
        __syncthreads();

        #pragma unroll
        for (int ks = 0; ks < 4; ks++) {
            int kb = ks * 8;
            unsigned af[4][4];
            #pragma unroll
            for (int mt = 0; mt < 4; mt++) {
                int m = wm + mt * 16 + g;
                af[mt][0] = AsM[m][kb + t];
                af[mt][1] = AsM[m + 8][kb + t];
                af[mt][2] = AsM[m][kb + t + 4];
                af[mt][3] = AsM[m + 8][kb + t + 4];
            }
            unsigned bf[4][2];
            #pragma unroll
            for (int nt = 0; nt < 4; nt++) {
                int n = wn + nt * 8 + g;
                if (BMODE == 1) {
                    bf[nt][0] = BsM[n * 36 + kb + t];
                    bf[nt][1] = BsM[n * 36 + kb + t + 4];
                } else {
                    bf[nt][0] = BsM[(kb + t) * 136 + n];
                    bf[nt][1] = BsM[(kb + t + 4) * 136 + n];
                }
            }
            #pragma unroll
            for (int mt = 0; mt < 4; mt++)
                #pragma unroll
                for (int nt = 0; nt < 4; nt++)
                    mma8(acc[mt][nt], af[mt], bf[nt]);
        }
        __syncthreads();
    }

    #pragma unroll
    for (int mt = 0; mt < 4; mt++) {
        int r0 = m0 + wm + mt * 16 + g;
        #pragma unroll
        for (int nt = 0; nt < 4; nt++) {
            int c0 = n0 + wn + nt * 8 + 2 * t;
            float2 v0 = make_float2(alpha * acc[mt][nt][0], alpha * acc[mt][nt][1]);
            float2 v1 = make_float2(alpha * acc[mt][nt][2], alpha * acc[mt][nt][3]);
            *reinterpret_cast<float2*>(C + (long)r0 * ldc + c0) = v0;
            *reinterpret_cast<float2*>(C + (long)(r0 + 8) * ldc + c0) = v1;
        }
    }
}

// ------------------------------ LSTM cell ----------------------------------
template <bool FIRST>
__global__ void k_cell(const float* __restrict__ bih, const float* __restrict__ bhh, int t)
{
    int idx = blockIdx.x * 256 + threadIdx.x;   // 4096*512
    int m = idx >> 9, j = idx & 511;
    const float* XWt = d_XW + (size_t)t * 4096 * 2048;
    size_t base = (size_t)m * 2048;
    float gi = XWt[base + j]        + bih[j]        + bhh[j];
    float gf = XWt[base + 512 + j]  + bih[512 + j]  + bhh[512 + j];
    float gg = XWt[base + 1024 + j] + bih[1024 + j] + bhh[1024 + j];
    float go = XWt[base + 1536 + j] + bih[1536 + j] + bhh[1536 + j];
    if (!FIRST) {
        gi += d_HG[base + j];
        gf += d_HG[base + 512 + j];
        gg += d_HG[base + 1024 + j];
        go += d_HG[base + 1536 + j];
    }
    float cn;
    if (FIRST) cn = sigf(gi) * tanhf(gg);
    else       cn = sigf(gf) * d_c[idx] + sigf(gi) * tanhf(gg);
    d_c[idx] = cn;
    d_h[idx] = sigf(go) * tanhf(cn);
}

__global__ void k_adj1(const float* __restrict__ supports, float* __restrict__ out_adj)
{
    int idx = blockIdx.x * 256 + threadIdx.x;
    float h = d_h[idx];
    out_adj[idx] = h;
    d_adj1[idx] = h * supports[idx];
}

__global__ void k_chebfix()
{
    int idx = blockIdx.x * 256 + threadIdx.x;   // 4096 = b*512+i
    int b = idx >> 9, i = idx & 511;
    d_T2[((size_t)b * 512 + i) * 512 + i] -= 1.f;
}

// GLU epilogue for GCN conv
__global__ void k_glu(const float* __restrict__ bias)
{
    int idx = blockIdx.x * 256 + threadIdx.x;   // 8*64*30720
    int n = idx % 30720;
    int bo = idx / 30720;
    int b = bo >> 6, o = bo & 63;
    size_t base = (size_t)b * 3932160;
    float f = d_xg[base + (size_t)o * 30720 + n] + bias[o];
    float gg = d_xg[base + (size_t)(o + 64) * 30720 + n] + bias[o + 64];
    d_x1b[(size_t)bo * 30720 + n] = sigf(gg) * lrelu(f);
}

// --------------------------- temporal attention ----------------------------
__global__ void k_f1(const float* __restrict__ tw1)
{
    int idx = blockIdx.x * 256 + threadIdx.x;   // 8*60*512
    int bl = idx >> 9, n = idx & 511;
    int b = bl / 60, l = bl - b * 60;
    const float* p = d_x1b + (size_t)b * 1966080 + n * 60 + l;
    float s = 0.f;
    #pragma unroll 8
    for (int c = 0; c < 64; c++) s += p[c * 30720] * tw1[c];
    d_f1[idx] = s;
}

__global__ void k_f2(const float* __restrict__ tw2)
{
    int bc = blockIdx.x;         // b*64+c
    int l = threadIdx.x;
    if (l >= 60) return;
    const float* p = d_x1b + (size_t)bc * 30720 + l;
    float s = 0.f;
    for (int n = 0; n < 512; n++) s += p[n * 60] * tw2[n];
    d_f2[bc * 60 + l] = s;
}

__global__ void k_tmp(const float* __restrict__ tw)
{
    int idx = blockIdx.x * 256 + threadIdx.x;   // 8*60*64
    int bl = idx >> 6, c = idx & 63;
    const float* f = d_f1 + bl * 512;
    float s = 0.f;
    for (int n = 0; n < 512; n++) s += f[n] * tw[n * 64 + c];
    d_tmp[idx] = s;
}

__global__ void k_lgb(const float* __restrict__ tbm)
{
    int idx = blockIdx.x * 256 + threadIdx.x;   // (b,l,q)
    if (idx >= 28800) return;
    int q = idx % 60; int bl = idx / 60;
    int l = bl % 60;
    int b = bl / 60;
    float s = 0.f;
    #pragma unroll 8
    for (int c = 0; c < 64; c++) s += d_tmp[bl * 64 + c] * d_f2[(b * 64 + c) * 60 + q];
    d_lgsig[idx] = sigf(s + tbm[l * 60 + q]);
}

__global__ void k_lgc(const float* __restrict__ tv)
{
    int idx = blockIdx.x * 256 + threadIdx.x;   // (b,i,t)
    if (idx >= 28800) return;
    int b = idx / 3600; int r = idx - b * 3600;
    int i = r / 60, t = r - i * 60;
    float s = 0.f;
    for (int q = 0; q < 60; q++) s += tv[i * 60 + q] * d_lgsig[(b * 60 + q) * 60 + t];
    d_lg2[idx] = s;
}

__global__ void k_bn()
{
    int t = blockIdx.x;
    __shared__ float ss[256], sq[256];
    float a = 0.f, b2 = 0.f;
    for (int s = threadIdx.x; s < 480; s += 256) {
        float v = d_lg2[s * 60 + t];
        a += v; b2 += v * v;
    }
    ss[threadIdx.x] = a; sq[threadIdx.x] = b2; __syncthreads();
    for (int st = 128; st > 0; st >>= 1) {
        if (threadIdx.x < st) { ss[threadIdx.x] += ss[threadIdx.x + st]; sq[threadIdx.x] += sq[threadIdx.x + st]; }
        __syncthreads();
    }
    if (threadIdx.x == 0) {
        float mu = ss[0] / 480.f;
        float var = sq[0] / 480.f - mu * mu;
        d_bn_mu[t] = mu;
        d_bn_rstd[t] = rsqrtf(var + 1e-5f);
    }
}

__global__ void k_soft(const float* __restrict__ bg, const float* __restrict__ bb, float* __restrict__ out_tc)
{
    int bi = blockIdx.x;             // b*60+i
    int i = bi % 60;
    int t = threadIdx.x;             // 64 threads
    __shared__ float sh[64];
    int blk_i = i < 12 ? 0 : (i < 24 ? 1 : (i < 36 ? 2 : 3));
    float z = -3.0e38f;
    if (t < 60) {
        float v = (d_lg2[bi * 60 + t] - d_bn_mu[t]) * d_bn_rstd[t] * bg[t] + bb[t];
        int blk_t = t < 12 ? 0 : (t < 24 ? 1 : (t < 36 ? 2 : 3));
        if (blk_t != blk_i) v += -1e13f;
        z = v;
    }
    sh[t] = z; __syncthreads();
    for (int s = 32; s > 0; s >>= 1) { if (t < s) sh[t] = fmaxf(sh[t], sh[t + s]); __syncthreads(); }
    float mx = sh[0]; __syncthreads();
    float e = (t < 60) ? expf(z - mx) : 0.f;
    sh[t] = e; __syncthreads();
    for (int s = 32; s > 0; s >>= 1) { if (t < s) sh[t] += sh[t + s]; __syncthreads(); }
    float inv = 1.f / sh[0];
    if (t < 60) {
        float val = e * inv;
        d_Tc[bi * 60 + t] = val;
        out_tc[bi * 60 + t] = val;
    }
}

// --------------------- x2 = x1b @ Tc^T  (SIMT, tiny) -----------------------
template <bool FULL>
__global__ void __launch_bounds__(256) k_sgemm(
    const float* __restrict__ A, const float* __restrict__ B, float* __restrict__ C,
    int M, int N, int K, int lda, int ldb, int ldc,
    long sA, long sB, long sC, int transB, float alpha)
{
    A += (long)blockIdx.z * sA;
    B += (long)blockIdx.z * sB;
    C += (long)blockIdx.z * sC;
    int m0 = blockIdx.y * 128, n0 = blockIdx.x * 128;
    __shared__ float As[16][132];
    __shared__ float Bs[16][132];
    int tid = threadIdx.x;
    int tx = tid & 15, ty = tid >> 4;
    float acc[8][8] = {};
    for (int k0 = 0; k0 < K; k0 += 16) {
        #pragma unroll
        for (int r = 0; r < 8; r++) {
            int e = tid + r * 256;
            int m = e >> 4, kk = e & 15;
            float v = (m0 + m < M && k0 + kk < K) ? A[(long)(m0 + m) * lda + (k0 + kk)] : 0.f;
            As[kk][m] = v;
        }
        if (!transB) {
            #pragma unroll
            for (int r = 0; r < 8; r++) {
                int e = tid + r * 256;
                int kk = e >> 7, n = e & 127;
                float v = (k0 + kk < K && n0 + n < N) ? B[(long)(k0 + kk) * ldb + (n0 + n)] : 0.f;
                Bs[kk][n] = v;
            }
        } else {
            #pragma unroll
            for (int r = 0; r < 8; r++) {
                int e = tid + r * 256;
                int n = e >> 4, kk = e & 15;
                float v = (n0 + n < N && k0 + kk < K) ? B[(long)(n0 + n) * ldb + (k0 + kk)] : 0.f;
                Bs[kk][n] = v;
            }
        }
        __syncthreads();
        #pragma unroll
        for (int kk = 0; kk < 16; kk++) {
            float a[8], bb[8];
            #pragma unroll
            for (int i = 0; i < 8; i++) a[i] = As[kk][ty * 8 + i];
            #pragma unroll
            for (int j = 0; j < 8; j++) bb[j] = Bs[kk][tx * 8 + j];
            #pragma unroll
            for (int i = 0; i < 8; i++)
                #pragma unroll
                for (int j = 0; j < 8; j++) acc[i][j] += a[i] * bb[j];
        }
        __syncthreads();
    }
    #pragma unroll
    for (int i = 0; i < 8; i++) {
        int m = m0 + ty * 8 + i;
        if (m >= M) continue;
        #pragma unroll
        for (int j = 0; j < 8; j++) {
            int n = n0 + tx * 8 + j;
            if (n < N) C[(long)m * ldc + n] = alpha * acc[i][j];
        }
    }
}

// ------------------- residual + per-b LayerNorm ----------------------------
__global__ void k_ystats()
{
    int b = blockIdx.y;
    int e = blockIdx.x * 256 + threadIdx.x;     // 1966080 exactly
    size_t g = (size_t)b * 1966080 + e;
    float v = lrelu(d_x2[g]) + d_x_in[g];
    d_x2[g] = v;
    __shared__ float ss[256], sq[256];
    ss[threadIdx.x] = v; sq[threadIdx.x] = v * v; __syncthreads();
    for (int s = 128; s > 0; s >>= 1) {
        if (threadIdx.x < s) { ss[threadIdx.x] += ss[threadIdx.x + s]; sq[threadIdx.x] += sq[threadIdx.x + s]; }
        __syncthreads();
    }
    if (threadIdx.x == 0) {
        d_psum[b * 7680 + blockIdx.x] = ss[0];
        d_psq [b * 7680 + blockIdx.x] = sq[0];
    }
}

__global__ void k_lnstats2()
{
    int b = blockIdx.x;
    __shared__ float ss[256], sq[256];
    float a = 0.f, b2 = 0.f;
    for (int i = threadIdx.x; i < 7680; i += 256) {
        a += d_psum[b * 7680 + i]; b2 += d_psq[b * 7680 + i];
    }
    ss[threadIdx.x] = a; sq[threadIdx.x] = b2; __syncthreads();
    for (int s = 128; s > 0; s >>= 1) {
        if (threadIdx.x < s) { ss[threadIdx.x] += ss[threadIdx.x + s]; sq[threadIdx.x] += sq[threadIdx.x + s]; }
        __syncthreads();
    }
    if (threadIdx.x == 0) {
        float mu = ss[0] / 1966080.f;
        float var = sq[0] / 1966080.f - mu * mu;
        d_mu[b] = mu;
        d_rstd[b] = rsqrtf(var + 1e-5f);
    }
}

__global__ void k_lnfinal(const float* __restrict__ g, const float* __restrict__ bb, float* __restrict__ out)
{
    int b = blockIdx.y;
    int e = blockIdx.x * 256 + threadIdx.x;
    size_t idx = (size_t)b * 1966080 + e;
    out[idx] = (d_x2[idx] - d_mu[b]) * d_rstd[b] * g[e] + bb[e];
}

// ------------------------------- launcher ----------------------------------
extern "C" void kernel_launch(void* const* d_in, const int* in_sizes, int n_in,
                              void* d_out, int out_size) {
    const float* x    = (const float*)d_in[0];
    const float* sup  = (const float*)d_in[1];
    const float* c1w  = (const float*)d_in[2];
    const float* c1b  = (const float*)d_in[3];
    const float* tw   = (const float*)d_in[4];
    const float* tb   = (const float*)d_in[5];
    const float* s3w1 = (const float*)d_in[6];
    const float* s3w2 = (const float*)d_in[7];
    const float* s2w1 = (const float*)d_in[8];
    const float* s2w2 = (const float*)d_in[9];
    const float* wih  = (const float*)d_in[10];
    const float* whh  = (const float*)d_in[11];
    const float* bih  = (const float*)d_in[12];
    const float* bhh  = (const float*)d_in[13];
    const float* gw   = (const float*)d_in[14];
    const float* gb   = (const float*)d_in[15];
    const float* tw1  = (const float*)d_in[16];
    const float* tw2  = (const float*)d_in[17];
    const float* twm  = (const float*)d_in[18];
    const float* tbm  = (const float*)d_in[19];
    const float* tv   = (const float*)d_in[20];
    const float* bng  = (const float*)d_in[21];
    const float* bnb  = (const float*)d_in[22];
    const float* lng  = (const float*)d_in[23];
    const float* lnb  = (const float*)d_in[24];
    float* out = (float*)d_out;

    float *pS, *pXW, *pHG, *pH, *pA1, *pT2, *pX1T, *pXG1, *pXG2, *pX1B, *pTc, *pX2, *pXG;
    cudaGetSymbolAddress((void**)&pS,   d_S);
    cudaGetSymbolAddress((void**)&pXW,  d_XW);
    cudaGetSymbolAddress((void**)&pHG,  d_HG);
    cudaGetSymbolAddress((void**)&pH,   d_h);
    cudaGetSymbolAddress((void**)&pA1,  d_adj1);
    cudaGetSymbolAddress((void**)&pT2,  d_T2);
    cudaGetSymbolAddress((void**)&pX1T, d_x1t);
    cudaGetSymbolAddress((void**)&pXG1, d_xgT1);
    cudaGetSymbolAddress((void**)&pXG2, d_xgT2);
    cudaGetSymbolAddress((void**)&pX1B, d_x1b);
    cudaGetSymbolAddress((void**)&pTc,  d_Tc);
    cudaGetSymbolAddress((void**)&pX2,  d_x2);
    cudaGetSymbolAddress((void**)&pXG,  d_xg);

    // ---- prep + attention -> S ----
    k_prep<<<dim3(512, 8), 256>>>(x, c1w, c1b, tw, tb, s3w1, s3w2, s2w1, s2w2);
    k_satt<<<dim3(16, 16, 128), dim3(32, 32)>>>();

    // ---- LSTM ----
    k_mma<1><<<dim3(16, 512, 1), 256>>>(pS, wih, pXW, 65536, 2048, 512,
                                        512, 512, 2048, 0, 0, 0, 1.f);
    k_cell<true><<<8192, 256>>>(bih, bhh, 0);
    for (int t = 1; t < 16; t++) {
        k_mma<1><<<dim3(16, 32, 1), 256>>>(pH, whh, pHG, 4096, 2048, 512,
                                           512, 512, 2048, 0, 0, 0, 1.f);
        k_cell<false><<<8192, 256>>>(bih, bhh, t);
    }

    // ---- Chebyshev + graph einsum ----
    k_adj1<<<8192, 256>>>(sup, out + OUT_ADJ);
    k_mma<0><<<dim3(4, 4, 8), 256>>>(pA1, pA1, pT2, 512, 512, 512,
                                     512, 512, 512, 262144, 262144, 262144, 2.f);
    k_chebfix<<<16, 256>>>();
    k_mma<0><<<dim3(30, 4, 8), 256>>>(pA1, pX1T, pXG1, 512, 3840, 512,
                                      512, 3840, 3840, 262144, 1966080, 1966080, 1.f);
    k_mma<0><<<dim3(30, 4, 8), 256>>>(pT2, pX1T, pXG2, 512, 3840, 512,
                                      512, 3840, 3840, 262144, 1966080, 1966080, 1.f);

    // ---- GCN conv (tensor-core, gathered B) + GLU ----
    k_mma<2><<<dim3(240, 1, 8), 256>>>(gw, gw, pXG, 128, 30720, 576,
                                       576, 0, 30720, 0, 0, 3932160, 1.f);
    k_glu<<<61440, 256>>>(gb);

    // ---- temporal attention ----
    k_f1<<<960, 256>>>(tw1);
    k_f2<<<512, 64>>>(tw2);
    k_tmp<<<120, 256>>>(twm);
    k_lgb<<<113, 256>>>(tbm);
    k_lgc<<<113, 256>>>(tv);
    k_bn<<<60, 256>>>();
    k_soft<<<480, 64>>>(bng, bnb, out + OUT_TC);

    // ---- x2 = x1b @ T_coef^T ----
    k_sgemm<false><<<dim3(1, 256, 8), 256>>>(pX1B, pTc, pX2, 32768, 60, 60,
                                             60, 60, 60, 1966080, 3600, 1966080, 1, 1.f);

    // ---- residual + LayerNorm ----
    k_ystats<<<dim3(7680, 8), 256>>>();
    k_lnstats2<<<8, 256>>>();
    k_lnfinal<<<dim3(7680, 8), 256>>>(lng, lnb, out);
}